// round 2
// baseline (speedup 1.0000x reference)
#include <cuda_runtime.h>
#include <cuda_bf16.h>
#include <math.h>

// Problem constants
#define Bb 8
#define Ee 256
#define BE 2048        // B*E
#define Nn 32
#define Dd 512
#define RDd 768
#define Rr 2000
#define Ll 2
#define Kk 8
#define Mm 32
#define HEADS 8
#define DH 64
#define HLLM 4096

// ---------------- scratch (device globals; no allocation allowed) -------------
__device__ float g_proj[Rr * Dd];        // projected relation table
__device__ float g_inv[Rr];              // 1/max(norm,1e-12) per relation
__device__ float g_states[BE * Dd];
__device__ float g_agg[BE * Dd];
__device__ float g_t1[BE * Dd];
__device__ float g_t2[BE * Dd];
__device__ float g_ffh[BE * 2048];
__device__ float g_k[BE * Dd];
__device__ float g_v[BE * Dd];
__device__ float g_q[Mm * Dd];
__device__ float g_mem[Bb * Mm * Dd];
__device__ float g_memo[Bb * Mm * Dd];
__device__ float g_keep[Bb];

// ---------------- generic SGEMM: C[M,N] = A[M,K] @ B[N,K]^T + bias, opt GELU --
// 128x64 block tile, BK=8, 128 threads, 8x8 microtile.
__global__ void __launch_bounds__(128) sgemm_kernel(
    const float* __restrict__ A, const float* __restrict__ B,
    const float* __restrict__ bias, float* __restrict__ C,
    int M, int N, int K, int act)
{
    __shared__ float As[8][128];
    __shared__ float Bs[8][64];
    const int bm = blockIdx.y * 128;
    const int bn = blockIdx.x * 64;
    const int tid = threadIdx.x;
    const int ty = tid >> 3;   // 0..15 -> 8 rows each
    const int tx = tid & 7;    // 0..7  -> 8 cols each

    float acc[8][8];
#pragma unroll
    for (int i = 0; i < 8; i++)
#pragma unroll
        for (int j = 0; j < 8; j++) acc[i][j] = 0.f;

    for (int k0 = 0; k0 < K; k0 += 8) {
        // A tile: 128 rows x 8 k -> 256 float4 loads, 2 per thread
#pragma unroll
        for (int v = 0; v < 2; v++) {
            int vid = tid + v * 128;
            int row = vid >> 1;
            int kp = (vid & 1) * 4;
            float4 a4 = make_float4(0.f, 0.f, 0.f, 0.f);
            int gm = bm + row;
            if (gm < M) a4 = *(const float4*)(A + (size_t)gm * K + k0 + kp);
            As[kp + 0][row] = a4.x;
            As[kp + 1][row] = a4.y;
            As[kp + 2][row] = a4.z;
            As[kp + 3][row] = a4.w;
        }
        // B tile: 64 rows x 8 k -> 128 float4 loads, 1 per thread
        {
            int row = tid >> 1;
            int kp = (tid & 1) * 4;
            float4 b4 = make_float4(0.f, 0.f, 0.f, 0.f);
            int gn = bn + row;
            if (gn < N) b4 = *(const float4*)(B + (size_t)gn * K + k0 + kp);
            Bs[kp + 0][row] = b4.x;
            Bs[kp + 1][row] = b4.y;
            Bs[kp + 2][row] = b4.z;
            Bs[kp + 3][row] = b4.w;
        }
        __syncthreads();
#pragma unroll
        for (int kk = 0; kk < 8; kk++) {
            float4 a0 = *(const float4*)&As[kk][ty * 8];
            float4 a1 = *(const float4*)&As[kk][ty * 8 + 4];
            float4 b0 = *(const float4*)&Bs[kk][tx * 8];
            float4 b1 = *(const float4*)&Bs[kk][tx * 8 + 4];
            float a[8] = {a0.x, a0.y, a0.z, a0.w, a1.x, a1.y, a1.z, a1.w};
            float b[8] = {b0.x, b0.y, b0.z, b0.w, b1.x, b1.y, b1.z, b1.w};
#pragma unroll
            for (int i = 0; i < 8; i++)
#pragma unroll
                for (int j = 0; j < 8; j++) acc[i][j] = fmaf(a[i], b[j], acc[i][j]);
        }
        __syncthreads();
    }

#pragma unroll
    for (int i = 0; i < 8; i++) {
        int gm = bm + ty * 8 + i;
        if (gm >= M) continue;
#pragma unroll
        for (int j = 0; j < 8; j++) {
            int gn = bn + tx * 8 + j;
            if (gn >= N) continue;
            float v = acc[i][j] + bias[gn];
            if (act == 1) {
                // exact gelu: 0.5*x*(1+erf(x/sqrt(2)))
                v = 0.5f * v * (1.f + erff(v * 0.70710678118654752440f));
            }
            C[(size_t)gm * N + gn] = v;
        }
    }
}

// ---------------- per-relation inverse norm -----------------------------------
__global__ void __launch_bounds__(128) invnorm_kernel(const float* __restrict__ proj,
                                                      float* __restrict__ inv)
{
    int r = blockIdx.x;
    int t = threadIdx.x;
    __shared__ float red[128];
    float s = 0.f;
    for (int i = t; i < Dd; i += 128) {
        float v = proj[(size_t)r * Dd + i];
        s += v * v;
    }
    red[t] = s;
    __syncthreads();
    for (int o = 64; o > 0; o >>= 1) {
        if (t < o) red[t] += red[t + o];
        __syncthreads();
    }
    if (t == 0) inv[r] = 1.f / fmaxf(sqrtf(red[0]), 1e-12f);
}

// ---------------- sims + top-k + aggregation (+ states init) ------------------
__global__ void __launch_bounds__(256) sim_topk_agg_kernel(
    const int* __restrict__ eids, const int* __restrict__ nids,
    const float* __restrict__ proj, const float* __restrict__ inv,
    float* __restrict__ states, float* __restrict__ agg)
{
    int be = blockIdx.x;
    int t = threadIdx.x;
    __shared__ float evec[Dd];
    __shared__ float sims[Nn];
    __shared__ int nid_s[Nn];
    __shared__ int sel[Kk];

    int eid = eids[be];
    for (int i = t; i < Dd; i += 256) {
        float v = proj[(size_t)eid * Dd + i];
        evec[i] = v;
        states[(size_t)be * Dd + i] = v;   // states initialized to rel_vec
    }
    if (t < Nn) nid_s[t] = nids[be * Nn + t];
    __syncthreads();

    int warp = t >> 5, lane = t & 31;
    float einv = inv[eid];
    for (int n = warp; n < Nn; n += 8) {
        int nid = nid_s[n];
        const float* nv = proj + (size_t)nid * Dd;
        float s = 0.f;
        for (int i = lane; i < Dd; i += 32) s += nv[i] * evec[i];
#pragma unroll
        for (int o = 16; o > 0; o >>= 1) s += __shfl_down_sync(0xffffffffu, s, o);
        if (lane == 0) sims[n] = s * einv * inv[nid];
    }
    __syncthreads();

    if (t == 0) {
        unsigned used = 0;
        for (int k = 0; k < Kk; k++) {
            float best = -1e30f;
            int bi = 0;
            for (int n = 0; n < Nn; n++) {
                if (used & (1u << n)) continue;
                if (sims[n] > best) { best = sims[n]; bi = n; }
            }
            used |= (1u << bi);
            sel[k] = nid_s[bi];
        }
    }
    __syncthreads();

    for (int i = t; i < Dd; i += 256) {
        float s = 0.f;
#pragma unroll
        for (int k = 0; k < Kk; k++) s += proj[(size_t)sel[k] * Dd + i];
        agg[(size_t)be * Dd + i] = s * 0.125f;
    }
}

// ---------------- residual add + layernorm (+ optional mask) ------------------
__global__ void __launch_bounds__(256) add_ln_kernel(
    const float* __restrict__ x, const float* __restrict__ r,
    const float* __restrict__ g, const float* __restrict__ b,
    const float* __restrict__ mask, float* __restrict__ out)
{
    int row = blockIdx.x;
    int t = threadIdx.x;
    __shared__ float red[256];
    size_t base = (size_t)row * Dd;
    float v0 = x[base + t] + r[base + t];
    float v1 = x[base + t + 256] + r[base + t + 256];

    red[t] = v0 + v1;
    __syncthreads();
    for (int o = 128; o > 0; o >>= 1) {
        if (t < o) red[t] += red[t + o];
        __syncthreads();
    }
    float mu = red[0] * (1.f / 512.f);
    __syncthreads();

    float d0 = v0 - mu, d1 = v1 - mu;
    red[t] = d0 * d0 + d1 * d1;
    __syncthreads();
    for (int o = 128; o > 0; o >>= 1) {
        if (t < o) red[t] += red[t + o];
        __syncthreads();
    }
    float var = red[0] * (1.f / 512.f);
    float is = rsqrtf(var + 1e-5f);
    float mk = mask ? mask[row] : 1.f;
    out[base + t]       = (d0 * is * g[t] + b[t]) * mk;
    out[base + t + 256] = (d1 * is * g[t + 256] + b[t + 256]) * mk;
}

// ---------------- memory-token cross attention --------------------------------
// grid (M, B), 256 threads: warp h handles head h for (b,m).
__global__ void __launch_bounds__(256) attn_kernel(
    const float* __restrict__ emask, const float* __restrict__ q,
    const float* __restrict__ kbuf, const float* __restrict__ vbuf,
    float* __restrict__ mem)
{
    int m = blockIdx.x, b = blockIdx.y;
    int h = threadIdx.x >> 5, lane = threadIdx.x & 31;
    __shared__ float w[HEADS][Ee];
    __shared__ float qs[HEADS][DH];

    for (int i = lane; i < DH; i += 32) qs[h][i] = q[(size_t)m * Dd + h * DH + i];
    __syncwarp();

    float sc[8];
#pragma unroll
    for (int i = 0; i < 8; i++) {
        int e = lane + i * 32;
        const float* kk = kbuf + ((size_t)(b * Ee + e)) * Dd + h * DH;
        float s = 0.f;
#pragma unroll
        for (int d = 0; d < DH; d += 4) {
            float4 kv = *(const float4*)(kk + d);
            float4 qv = *(const float4*)(&qs[h][d]);
            s += qv.x * kv.x + qv.y * kv.y + qv.z * kv.z + qv.w * kv.w;
        }
        s *= 0.125f;  // 1/sqrt(64)
        if (emask[b * Ee + e] == 0.f) s = -3.402823466e38f;
        sc[i] = s;
    }
    float mx = sc[0];
#pragma unroll
    for (int i = 1; i < 8; i++) mx = fmaxf(mx, sc[i]);
#pragma unroll
    for (int o = 16; o > 0; o >>= 1) mx = fmaxf(mx, __shfl_xor_sync(0xffffffffu, mx, o));
    float sum = 0.f;
#pragma unroll
    for (int i = 0; i < 8; i++) {
        sc[i] = expf(sc[i] - mx);
        sum += sc[i];
    }
#pragma unroll
    for (int o = 16; o > 0; o >>= 1) sum += __shfl_xor_sync(0xffffffffu, sum, o);
    float invs = 1.f / sum;
#pragma unroll
    for (int i = 0; i < 8; i++) w[h][lane + i * 32] = sc[i] * invs;
    __syncwarp();

    int d0 = lane * 2;
    float o0 = 0.f, o1 = 0.f;
    for (int e = 0; e < Ee; e++) {
        float we = w[h][e];
        const float2 vv = *(const float2*)(vbuf + ((size_t)(b * Ee + e)) * Dd + h * DH + d0);
        o0 = fmaf(we, vv.x, o0);
        o1 = fmaf(we, vv.y, o1);
    }
    size_t ob = ((size_t)(b * Mm + m)) * Dd + h * DH + d0;
    mem[ob] = o0;
    mem[ob + 1] = o1;
}

// ---------------- no-edge flag + row scaling ----------------------------------
__global__ void __launch_bounds__(256) keep_kernel(const float* __restrict__ emask,
                                                   float* __restrict__ keep)
{
    int b = blockIdx.x, t = threadIdx.x;
    __shared__ float red[256];
    red[t] = emask[b * Ee + t];
    __syncthreads();
    for (int o = 128; o > 0; o >>= 1) {
        if (t < o) red[t] += red[t + o];
        __syncthreads();
    }
    if (t == 0) keep[b] = (red[0] == 0.f) ? 0.f : 1.f;
}

__global__ void __launch_bounds__(256) scale_rows_kernel(float* __restrict__ memo,
                                                         const float* __restrict__ keep)
{
    int row = blockIdx.x, t = threadIdx.x;
    float kf = keep[row >> 5];   // row = b*32+m
    memo[(size_t)row * Dd + t] *= kf;
    memo[(size_t)row * Dd + t + 256] *= kf;
}

// ---------------- launch ------------------------------------------------------
static inline dim3 gemm_grid(int M, int N) { return dim3((N + 63) / 64, (M + 127) / 128); }

extern "C" void kernel_launch(void* const* d_in, const int* in_sizes, int n_in,
                              void* d_out, int out_size)
{
    const int*   eids    = (const int*)d_in[0];
    const int*   nids    = (const int*)d_in[1];
    const float* emask   = (const float*)d_in[2];
    const float* rel_emb = (const float*)d_in[3];
    const float* rp_w    = (const float*)d_in[4];
    const float* rp_b    = (const float*)d_in[5];
    const float* ly_vw   = (const float*)d_in[6];
    const float* ly_vb   = (const float*)d_in[7];
    const float* ly_ow   = (const float*)d_in[8];
    const float* ly_ob   = (const float*)d_in[9];
    const float* ly_n1g  = (const float*)d_in[10];
    const float* ly_n1b  = (const float*)d_in[11];
    const float* ly_n2g  = (const float*)d_in[12];
    const float* ly_n2b  = (const float*)d_in[13];
    const float* ly_w1   = (const float*)d_in[14];
    const float* ly_b1   = (const float*)d_in[15];
    const float* ly_w2   = (const float*)d_in[16];
    const float* ly_b2   = (const float*)d_in[17];
    const float* mem_q   = (const float*)d_in[18];
    const float* t_qw    = (const float*)d_in[19];
    const float* t_qb    = (const float*)d_in[20];
    const float* t_kw    = (const float*)d_in[21];
    const float* t_kb    = (const float*)d_in[22];
    const float* t_vw    = (const float*)d_in[23];
    const float* t_vb    = (const float*)d_in[24];
    const float* t_ow    = (const float*)d_in[25];
    const float* t_ob    = (const float*)d_in[26];
    const float* proj_w  = (const float*)d_in[27];
    const float* proj_b  = (const float*)d_in[28];
    float* out = (float*)d_out;

    float *proj, *inv, *states, *agg, *t1, *t2, *ffh, *kb, *vb, *qb, *mem, *memo, *keep;
    cudaGetSymbolAddress((void**)&proj,   g_proj);
    cudaGetSymbolAddress((void**)&inv,    g_inv);
    cudaGetSymbolAddress((void**)&states, g_states);
    cudaGetSymbolAddress((void**)&agg,    g_agg);
    cudaGetSymbolAddress((void**)&t1,     g_t1);
    cudaGetSymbolAddress((void**)&t2,     g_t2);
    cudaGetSymbolAddress((void**)&ffh,    g_ffh);
    cudaGetSymbolAddress((void**)&kb,     g_k);
    cudaGetSymbolAddress((void**)&vb,     g_v);
    cudaGetSymbolAddress((void**)&qb,     g_q);
    cudaGetSymbolAddress((void**)&mem,    g_mem);
    cudaGetSymbolAddress((void**)&memo,   g_memo);
    cudaGetSymbolAddress((void**)&keep,   g_keep);

    // 1. project the relation table once (R x D, K=RD)
    sgemm_kernel<<<gemm_grid(Rr, Dd), 128>>>(rel_emb, rp_w, rp_b, proj, Rr, Dd, RDd, 0);
    invnorm_kernel<<<Rr, 128>>>(proj, inv);

    // 2. sims + top-k + aggregation (+ states := rel_vec)
    sim_topk_agg_kernel<<<BE, 256>>>(eids, nids, proj, inv, states, agg);

    // 3. relation context layers
    for (int l = 0; l < Ll; l++) {
        const float* vw  = ly_vw + (size_t)l * Dd * Dd;
        const float* vbi = ly_vb + (size_t)l * Dd;
        const float* ow  = ly_ow + (size_t)l * Dd * Dd;
        const float* ob  = ly_ob + (size_t)l * Dd;
        const float* n1g = ly_n1g + (size_t)l * Dd;
        const float* n1b = ly_n1b + (size_t)l * Dd;
        const float* n2g = ly_n2g + (size_t)l * Dd;
        const float* n2b = ly_n2b + (size_t)l * Dd;
        const float* w1  = ly_w1 + (size_t)l * 4 * Dd * Dd;
        const float* b1  = ly_b1 + (size_t)l * 4 * Dd;
        const float* w2  = ly_w2 + (size_t)l * Dd * 4 * Dd;
        const float* b2  = ly_b2 + (size_t)l * Dd;

        sgemm_kernel<<<gemm_grid(BE, Dd), 128>>>(agg, vw, vbi, t1, BE, Dd, Dd, 0);
        sgemm_kernel<<<gemm_grid(BE, Dd), 128>>>(t1, ow, ob, t2, BE, Dd, Dd, 0);
        add_ln_kernel<<<BE, 256>>>(states, t2, n1g, n1b, nullptr, states);
        sgemm_kernel<<<gemm_grid(BE, 4 * Dd), 128>>>(states, w1, b1, ffh, BE, 4 * Dd, Dd, 1);
        sgemm_kernel<<<gemm_grid(BE, Dd), 128>>>(ffh, w2, b2, t2, BE, Dd, 4 * Dd, 0);
        add_ln_kernel<<<BE, 256>>>(states, t2, n2g, n2b, emask, states);
    }

    // 4. tokenizer projections
    sgemm_kernel<<<gemm_grid(BE, Dd), 128>>>(states, t_kw, t_kb, kb, BE, Dd, Dd, 0);
    sgemm_kernel<<<gemm_grid(BE, Dd), 128>>>(states, t_vw, t_vb, vb, BE, Dd, Dd, 0);
    sgemm_kernel<<<gemm_grid(Mm, Dd), 128>>>(mem_q, t_qw, t_qb, qb, Mm, Dd, Dd, 0);

    // 5. cross attention
    attn_kernel<<<dim3(Mm, Bb), 256>>>(emask, qb, kb, vb, mem);

    // 6. out proj + no-edge zeroing + llm projection
    keep_kernel<<<Bb, 256>>>(emask, keep);
    sgemm_kernel<<<gemm_grid(Bb * Mm, Dd), 128>>>(mem, t_ow, t_ob, memo, Bb * Mm, Dd, Dd, 0);
    scale_rows_kernel<<<Bb * Mm, 256>>>(memo, keep);
    sgemm_kernel<<<gemm_grid(Bb * Mm, HLLM), 128>>>(memo, proj_w, proj_b, out, Bb * Mm, HLLM, Dd, 0);
}

// round 6
// speedup vs baseline: 1.2601x; 1.2601x over previous
#include <cuda_runtime.h>
#include <cuda_bf16.h>
#include <math.h>
#include <stdint.h>

// Problem constants
#define Bb 8
#define Ee 256
#define BE 2048        // B*E
#define Nn 32
#define Dd 512
#define RDd 768
#define Rr 2000
#define Ll 2
#define Kk 8
#define Mm 32
#define HEADS 8
#define DH 64
#define HLLM 4096

// ---------------- scratch (device globals; no allocation allowed) -------------
__device__ float g_proj[Rr * Dd];        // projected relation table
__device__ float g_inv[Rr];              // 1/max(norm,1e-12) per relation
__device__ float g_states[BE * Dd];
__device__ float g_agg[BE * Dd];
__device__ float g_t1[BE * Dd];
__device__ float g_t2[BE * Dd];
__device__ float g_ffh[BE * 2048];
__device__ float g_k[BE * Dd];
__device__ float g_v[BE * Dd];
__device__ float g_q[Mm * Dd];
__device__ float g_mem[Bb * Mm * Dd];
__device__ float g_memo[Bb * Mm * Dd];
__device__ float g_keep[Bb];

// ---------------- tf32 helpers ------------------------------------------------
__device__ __forceinline__ uint32_t f2tf32(float x) {
    uint32_t u;
    asm("cvt.rna.tf32.f32 %0, %1;" : "=r"(u) : "f"(x));
    return u;
}

__device__ __forceinline__ void mma_tf32(float* d, const uint32_t* a, const uint32_t* b) {
    asm volatile(
        "mma.sync.aligned.m16n8k8.row.col.f32.tf32.tf32.f32 "
        "{%0,%1,%2,%3}, {%4,%5,%6,%7}, {%8,%9}, {%0,%1,%2,%3};"
        : "+f"(d[0]), "+f"(d[1]), "+f"(d[2]), "+f"(d[3])
        : "r"(a[0]), "r"(a[1]), "r"(a[2]), "r"(a[3]), "r"(b[0]), "r"(b[1]));
}

// ---------------- tf32 tensor-core GEMM: C[M,N] = A[M,K] @ B[N,K]^T + bias ----
// Requires: M % BM == 0, N % BN == 0, K % 32 == 0. 256 threads, 8 warps.
// Warp grid (BM/WM) x (BN/WN) must be 8. BK = 32.
template<int BM, int BN, int WM, int WN>
__global__ void __launch_bounds__(256) tf32_gemm_kernel(
    const float* __restrict__ A, const float* __restrict__ B,
    const float* __restrict__ bias, float* __restrict__ C,
    int M, int N, int K, int act)
{
    constexpr int BK = 32;
    constexpr int LDS_ = BK + 4;        // 36: bank = (4*row + col) % 32 -> conflict-free frags
    constexpr int WCOLS = BN / WN;
    constexpr int MF = WM / 16;
    constexpr int NF = WN / 8;

    __shared__ uint32_t As[BM][LDS_];
    __shared__ uint32_t Bs[BN][LDS_];

    const int bm = blockIdx.y * BM;
    const int bn = blockIdx.x * BN;
    const int tid = threadIdx.x;
    const int warp = tid >> 5, lane = tid & 31;
    const int wm = (warp / WCOLS) * WM;
    const int wn = (warp % WCOLS) * WN;
    const int g = lane >> 2, tg = lane & 3;

    float acc[MF][NF][4];
#pragma unroll
    for (int f = 0; f < MF; f++)
#pragma unroll
        for (int j = 0; j < NF; j++)
#pragma unroll
            for (int c = 0; c < 4; c++) acc[f][j][c] = 0.f;

    for (int k0 = 0; k0 < K; k0 += BK) {
        // A tile: BM x 32 floats = BM*8 float4
#pragma unroll
        for (int i = tid; i < BM * 8; i += 256) {
            int row = i >> 3, c4 = (i & 7) << 2;
            float4 v = *(const float4*)(A + (size_t)(bm + row) * K + k0 + c4);
            As[row][c4 + 0] = f2tf32(v.x);
            As[row][c4 + 1] = f2tf32(v.y);
            As[row][c4 + 2] = f2tf32(v.z);
            As[row][c4 + 3] = f2tf32(v.w);
        }
#pragma unroll
        for (int i = tid; i < BN * 8; i += 256) {
            int row = i >> 3, c4 = (i & 7) << 2;
            float4 v = *(const float4*)(B + (size_t)(bn + row) * K + k0 + c4);
            Bs[row][c4 + 0] = f2tf32(v.x);
            Bs[row][c4 + 1] = f2tf32(v.y);
            Bs[row][c4 + 2] = f2tf32(v.z);
            Bs[row][c4 + 3] = f2tf32(v.w);
        }
        __syncthreads();

#pragma unroll
        for (int kk = 0; kk < 4; kk++) {
            uint32_t afr[MF][4], bfr[NF][2];
#pragma unroll
            for (int f = 0; f < MF; f++) {
                int rm = wm + f * 16;
                afr[f][0] = As[rm + g][kk * 8 + tg];
                afr[f][1] = As[rm + g + 8][kk * 8 + tg];
                afr[f][2] = As[rm + g][kk * 8 + tg + 4];
                afr[f][3] = As[rm + g + 8][kk * 8 + tg + 4];
            }
#pragma unroll
            for (int j = 0; j < NF; j++) {
                int nb = wn + j * 8 + g;
                bfr[j][0] = Bs[nb][kk * 8 + tg];
                bfr[j][1] = Bs[nb][kk * 8 + tg + 4];
            }
#pragma unroll
            for (int f = 0; f < MF; f++)
#pragma unroll
                for (int j = 0; j < NF; j++)
                    mma_tf32(acc[f][j], afr[f], bfr[j]);
        }
        __syncthreads();
    }

    // epilogue: bias (+ optional exact gelu)
#pragma unroll
    for (int f = 0; f < MF; f++) {
        int row0 = bm + wm + f * 16 + g;
#pragma unroll
        for (int j = 0; j < NF; j++) {
            int col = bn + wn + j * 8 + tg * 2;
            float bv0 = bias[col], bv1 = bias[col + 1];
            float c0 = acc[f][j][0] + bv0;
            float c1 = acc[f][j][1] + bv1;
            float c2 = acc[f][j][2] + bv0;
            float c3 = acc[f][j][3] + bv1;
            if (act == 1) {
                c0 = 0.5f * c0 * (1.f + erff(c0 * 0.70710678118654752440f));
                c1 = 0.5f * c1 * (1.f + erff(c1 * 0.70710678118654752440f));
                c2 = 0.5f * c2 * (1.f + erff(c2 * 0.70710678118654752440f));
                c3 = 0.5f * c3 * (1.f + erff(c3 * 0.70710678118654752440f));
            }
            *(float2*)(C + (size_t)row0 * N + col) = make_float2(c0, c1);
            *(float2*)(C + (size_t)(row0 + 8) * N + col) = make_float2(c2, c3);
        }
    }
}

// ---------------- fp32 SGEMM (exact path + small matrices) --------------------
// 128x64 block tile, BK=8, 128 threads, 8x8 microtile.
__global__ void __launch_bounds__(128) sgemm_kernel(
    const float* __restrict__ A, const float* __restrict__ B,
    const float* __restrict__ bias, float* __restrict__ C,
    int M, int N, int K, int act)
{
    __shared__ float As[8][128];
    __shared__ float Bs[8][64];
    const int bm = blockIdx.y * 128;
    const int bn = blockIdx.x * 64;
    const int tid = threadIdx.x;
    const int ty = tid >> 3;
    const int tx = tid & 7;

    float acc[8][8];
#pragma unroll
    for (int i = 0; i < 8; i++)
#pragma unroll
        for (int j = 0; j < 8; j++) acc[i][j] = 0.f;

    for (int k0 = 0; k0 < K; k0 += 8) {
#pragma unroll
        for (int v = 0; v < 2; v++) {
            int vid = tid + v * 128;
            int row = vid >> 1;
            int kp = (vid & 1) * 4;
            float4 a4 = make_float4(0.f, 0.f, 0.f, 0.f);
            int gm = bm + row;
            if (gm < M) a4 = *(const float4*)(A + (size_t)gm * K + k0 + kp);
            As[kp + 0][row] = a4.x;
            As[kp + 1][row] = a4.y;
            As[kp + 2][row] = a4.z;
            As[kp + 3][row] = a4.w;
        }
        {
            int row = tid >> 1;
            int kp = (tid & 1) * 4;
            float4 b4 = make_float4(0.f, 0.f, 0.f, 0.f);
            int gn = bn + row;
            if (gn < N) b4 = *(const float4*)(B + (size_t)gn * K + k0 + kp);
            Bs[kp + 0][row] = b4.x;
            Bs[kp + 1][row] = b4.y;
            Bs[kp + 2][row] = b4.z;
            Bs[kp + 3][row] = b4.w;
        }
        __syncthreads();
#pragma unroll
        for (int kk = 0; kk < 8; kk++) {
            float4 a0 = *(const float4*)&As[kk][ty * 8];
            float4 a1 = *(const float4*)&As[kk][ty * 8 + 4];
            float4 b0 = *(const float4*)&Bs[kk][tx * 8];
            float4 b1 = *(const float4*)&Bs[kk][tx * 8 + 4];
            float a[8] = {a0.x, a0.y, a0.z, a0.w, a1.x, a1.y, a1.z, a1.w};
            float b[8] = {b0.x, b0.y, b0.z, b0.w, b1.x, b1.y, b1.z, b1.w};
#pragma unroll
            for (int i = 0; i < 8; i++)
#pragma unroll
                for (int j = 0; j < 8; j++) acc[i][j] = fmaf(a[i], b[j], acc[i][j]);
        }
        __syncthreads();
    }

#pragma unroll
    for (int i = 0; i < 8; i++) {
        int gm = bm + ty * 8 + i;
        if (gm >= M) continue;
#pragma unroll
        for (int j = 0; j < 8; j++) {
            int gn = bn + tx * 8 + j;
            if (gn >= N) continue;
            float v = acc[i][j] + bias[gn];
            if (act == 1) v = 0.5f * v * (1.f + erff(v * 0.70710678118654752440f));
            C[(size_t)gm * N + gn] = v;
        }
    }
}

// ---------------- per-relation inverse norm -----------------------------------
__global__ void __launch_bounds__(128) invnorm_kernel(const float* __restrict__ proj,
                                                      float* __restrict__ inv)
{
    int r = blockIdx.x;
    int t = threadIdx.x;
    __shared__ float red[128];
    float s = 0.f;
    for (int i = t; i < Dd; i += 128) {
        float v = proj[(size_t)r * Dd + i];
        s += v * v;
    }
    red[t] = s;
    __syncthreads();
    for (int o = 64; o > 0; o >>= 1) {
        if (t < o) red[t] += red[t + o];
        __syncthreads();
    }
    if (t == 0) inv[r] = 1.f / fmaxf(sqrtf(red[0]), 1e-12f);
}

// ---------------- sims + top-k + aggregation (+ states init) ------------------
__global__ void __launch_bounds__(256) sim_topk_agg_kernel(
    const int* __restrict__ eids, const int* __restrict__ nids,
    const float* __restrict__ proj, const float* __restrict__ inv,
    float* __restrict__ states, float* __restrict__ agg)
{
    int be = blockIdx.x;
    int t = threadIdx.x;
    __shared__ float evec[Dd];
    __shared__ float sims[Nn];
    __shared__ int nid_s[Nn];
    __shared__ int sel[Kk];

    int eid = eids[be];
    for (int i = t; i < Dd; i += 256) {
        float v = proj[(size_t)eid * Dd + i];
        evec[i] = v;
        states[(size_t)be * Dd + i] = v;
    }
    if (t < Nn) nid_s[t] = nids[be * Nn + t];
    __syncthreads();

    int warp = t >> 5, lane = t & 31;
    float einv = inv[eid];
    for (int n = warp; n < Nn; n += 8) {
        int nid = nid_s[n];
        const float* nv = proj + (size_t)nid * Dd;
        float s = 0.f;
        for (int i = lane; i < Dd; i += 32) s += nv[i] * evec[i];
#pragma unroll
        for (int o = 16; o > 0; o >>= 1) s += __shfl_down_sync(0xffffffffu, s, o);
        if (lane == 0) sims[n] = s * einv * inv[nid];
    }
    __syncthreads();

    if (t == 0) {
        unsigned used = 0;
        for (int k = 0; k < Kk; k++) {
            float best = -1e30f;
            int bi = 0;
            for (int n = 0; n < Nn; n++) {
                if (used & (1u << n)) continue;
                if (sims[n] > best) { best = sims[n]; bi = n; }
            }
            used |= (1u << bi);
            sel[k] = nid_s[bi];
        }
    }
    __syncthreads();

    for (int i = t; i < Dd; i += 256) {
        float s = 0.f;
#pragma unroll
        for (int k = 0; k < Kk; k++) s += proj[(size_t)sel[k] * Dd + i];
        agg[(size_t)be * Dd + i] = s * 0.125f;
    }
}

// ---------------- residual add + layernorm (+ optional mask) ------------------
__global__ void __launch_bounds__(256) add_ln_kernel(
    const float* __restrict__ x, const float* __restrict__ r,
    const float* __restrict__ g, const float* __restrict__ b,
    const float* __restrict__ mask, float* __restrict__ out)
{
    int row = blockIdx.x;
    int t = threadIdx.x;
    __shared__ float red[256];
    size_t base = (size_t)row * Dd;
    float v0 = x[base + t] + r[base + t];
    float v1 = x[base + t + 256] + r[base + t + 256];

    red[t] = v0 + v1;
    __syncthreads();
    for (int o = 128; o > 0; o >>= 1) {
        if (t < o) red[t] += red[t + o];
        __syncthreads();
    }
    float mu = red[0] * (1.f / 512.f);
    __syncthreads();

    float d0 = v0 - mu, d1 = v1 - mu;
    red[t] = d0 * d0 + d1 * d1;
    __syncthreads();
    for (int o = 128; o > 0; o >>= 1) {
        if (t < o) red[t] += red[t + o];
        __syncthreads();
    }
    float var = red[0] * (1.f / 512.f);
    float is = rsqrtf(var + 1e-5f);
    float mk = mask ? mask[row] : 1.f;
    out[base + t]       = (d0 * is * g[t] + b[t]) * mk;
    out[base + t + 256] = (d1 * is * g[t + 256] + b[t + 256]) * mk;
}

// ---------------- memory-token cross attention --------------------------------
__global__ void __launch_bounds__(256) attn_kernel(
    const float* __restrict__ emask, const float* __restrict__ q,
    const float* __restrict__ kbuf, const float* __restrict__ vbuf,
    float* __restrict__ mem)
{
    int m = blockIdx.x, b = blockIdx.y;
    int h = threadIdx.x >> 5, lane = threadIdx.x & 31;
    __shared__ float w[HEADS][Ee];
    __shared__ float qs[HEADS][DH];

    for (int i = lane; i < DH; i += 32) qs[h][i] = q[(size_t)m * Dd + h * DH + i];
    __syncwarp();

    float sc[8];
#pragma unroll
    for (int i = 0; i < 8; i++) {
        int e = lane + i * 32;
        const float* kk = kbuf + ((size_t)(b * Ee + e)) * Dd + h * DH;
        float s = 0.f;
#pragma unroll
        for (int d = 0; d < DH; d += 4) {
            float4 kv = *(const float4*)(kk + d);
            float4 qv = *(const float4*)(&qs[h][d]);
            s += qv.x * kv.x + qv.y * kv.y + qv.z * kv.z + qv.w * kv.w;
        }
        s *= 0.125f;
        if (emask[b * Ee + e] == 0.f) s = -3.402823466e38f;
        sc[i] = s;
    }
    float mx = sc[0];
#pragma unroll
    for (int i = 1; i < 8; i++) mx = fmaxf(mx, sc[i]);
#pragma unroll
    for (int o = 16; o > 0; o >>= 1) mx = fmaxf(mx, __shfl_xor_sync(0xffffffffu, mx, o));
    float sum = 0.f;
#pragma unroll
    for (int i = 0; i < 8; i++) {
        sc[i] = expf(sc[i] - mx);
        sum += sc[i];
    }
#pragma unroll
    for (int o = 16; o > 0; o >>= 1) sum += __shfl_xor_sync(0xffffffffu, sum, o);
    float invs = 1.f / sum;
#pragma unroll
    for (int i = 0; i < 8; i++) w[h][lane + i * 32] = sc[i] * invs;
    __syncwarp();

    int d0 = lane * 2;
    float o0 = 0.f, o1 = 0.f;
    for (int e = 0; e < Ee; e++) {
        float we = w[h][e];
        const float2 vv = *(const float2*)(vbuf + ((size_t)(b * Ee + e)) * Dd + h * DH + d0);
        o0 = fmaf(we, vv.x, o0);
        o1 = fmaf(we, vv.y, o1);
    }
    size_t ob = ((size_t)(b * Mm + m)) * Dd + h * DH + d0;
    mem[ob] = o0;
    mem[ob + 1] = o1;
}

// ---------------- no-edge flag + row scaling ----------------------------------
__global__ void __launch_bounds__(256) keep_kernel(const float* __restrict__ emask,
                                                   float* __restrict__ keep)
{
    int b = blockIdx.x, t = threadIdx.x;
    __shared__ float red[256];
    red[t] = emask[b * Ee + t];
    __syncthreads();
    for (int o = 128; o > 0; o >>= 1) {
        if (t < o) red[t] += red[t + o];
        __syncthreads();
    }
    if (t == 0) keep[b] = (red[0] == 0.f) ? 0.f : 1.f;
}

__global__ void __launch_bounds__(256) scale_rows_kernel(float* __restrict__ memo,
                                                         const float* __restrict__ keep)
{
    int row = blockIdx.x, t = threadIdx.x;
    float kf = keep[row >> 5];
    memo[(size_t)row * Dd + t] *= kf;
    memo[(size_t)row * Dd + t + 256] *= kf;
}

// ---------------- launch ------------------------------------------------------
static inline dim3 gemm_grid(int M, int N) { return dim3((N + 63) / 64, (M + 127) / 128); }

// tf32 launchers (M % BM == 0, N % BN == 0, K % 32 == 0 guaranteed by caller)
static inline void tf32_big(const float* A, const float* B, const float* bias, float* C,
                            int M, int N, int K, int act) {
    tf32_gemm_kernel<128, 128, 64, 32><<<dim3(N / 128, M / 128), 256>>>(A, B, bias, C, M, N, K, act);
}
static inline void tf32_small(const float* A, const float* B, const float* bias, float* C,
                              int M, int N, int K, int act) {
    tf32_gemm_kernel<64, 64, 32, 16><<<dim3(N / 64, M / 64), 256>>>(A, B, bias, C, M, N, K, act);
}

extern "C" void kernel_launch(void* const* d_in, const int* in_sizes, int n_in,
                              void* d_out, int out_size)
{
    const int*   eids    = (const int*)d_in[0];
    const int*   nids    = (const int*)d_in[1];
    const float* emask   = (const float*)d_in[2];
    const float* rel_emb = (const float*)d_in[3];
    const float* rp_w    = (const float*)d_in[4];
    const float* rp_b    = (const float*)d_in[5];
    const float* ly_vw   = (const float*)d_in[6];
    const float* ly_vb   = (const float*)d_in[7];
    const float* ly_ow   = (const float*)d_in[8];
    const float* ly_ob   = (const float*)d_in[9];
    const float* ly_n1g  = (const float*)d_in[10];
    const float* ly_n1b  = (const float*)d_in[11];
    const float* ly_n2g  = (const float*)d_in[12];
    const float* ly_n2b  = (const float*)d_in[13];
    const float* ly_w1   = (const float*)d_in[14];
    const float* ly_b1   = (const float*)d_in[15];
    const float* ly_w2   = (const float*)d_in[16];
    const float* ly_b2   = (const float*)d_in[17];
    const float* mem_q   = (const float*)d_in[18];
    const float* t_qw    = (const float*)d_in[19];
    const float* t_qb    = (const float*)d_in[20];
    const float* t_kw    = (const float*)d_in[21];
    const float* t_kb    = (const float*)d_in[22];
    const float* t_vw    = (const float*)d_in[23];
    const float* t_vb    = (const float*)d_in[24];
    const float* t_ow    = (const float*)d_in[25];
    const float* t_ob    = (const float*)d_in[26];
    const float* proj_w  = (const float*)d_in[27];
    const float* proj_b  = (const float*)d_in[28];
    float* out = (float*)d_out;

    float *proj, *inv, *states, *agg, *t1, *t2, *ffh, *kb, *vb, *qb, *mem, *memo, *keep;
    cudaGetSymbolAddress((void**)&proj,   g_proj);
    cudaGetSymbolAddress((void**)&inv,    g_inv);
    cudaGetSymbolAddress((void**)&states, g_states);
    cudaGetSymbolAddress((void**)&agg,    g_agg);
    cudaGetSymbolAddress((void**)&t1,     g_t1);
    cudaGetSymbolAddress((void**)&t2,     g_t2);
    cudaGetSymbolAddress((void**)&ffh,    g_ffh);
    cudaGetSymbolAddress((void**)&kb,     g_k);
    cudaGetSymbolAddress((void**)&vb,     g_v);
    cudaGetSymbolAddress((void**)&qb,     g_q);
    cudaGetSymbolAddress((void**)&mem,    g_mem);
    cudaGetSymbolAddress((void**)&memo,   g_memo);
    cudaGetSymbolAddress((void**)&keep,   g_keep);

    // 1. project the relation table once (R x D, K=RD) -- EXACT fp32 so that the
    //    discrete top-k selection matches the reference bit-for-bit.
    sgemm_kernel<<<gemm_grid(Rr, Dd), 128>>>(rel_emb, rp_w, rp_b, proj, Rr, Dd, RDd, 0);
    invnorm_kernel<<<Rr, 128>>>(proj, inv);

    // 2. sims + top-k + aggregation (+ states := rel_vec)
    sim_topk_agg_kernel<<<BE, 256>>>(eids, nids, proj, inv, states, agg);

    // 3. relation context layers (tf32 tensor cores; smooth error only)
    for (int l = 0; l < Ll; l++) {
        const float* vw  = ly_vw + (size_t)l * Dd * Dd;
        const float* vbi = ly_vb + (size_t)l * Dd;
        const float* ow  = ly_ow + (size_t)l * Dd * Dd;
        const float* ob  = ly_ob + (size_t)l * Dd;
        const float* n1g = ly_n1g + (size_t)l * Dd;
        const float* n1b = ly_n1b + (size_t)l * Dd;
        const float* n2g = ly_n2g + (size_t)l * Dd;
        const float* n2b = ly_n2b + (size_t)l * Dd;
        const float* w1  = ly_w1 + (size_t)l * 4 * Dd * Dd;
        const float* b1  = ly_b1 + (size_t)l * 4 * Dd;
        const float* w2  = ly_w2 + (size_t)l * Dd * 4 * Dd;
        const float* b2  = ly_b2 + (size_t)l * Dd;

        tf32_big(agg, vw, vbi, t1, BE, Dd, Dd, 0);
        tf32_big(t1, ow, ob, t2, BE, Dd, Dd, 0);
        add_ln_kernel<<<BE, 256>>>(states, t2, n1g, n1b, nullptr, states);
        tf32_big(states, w1, b1, ffh, BE, 4 * Dd, Dd, 1);
        tf32_big(ffh, w2, b2, t2, BE, Dd, 4 * Dd, 0);
        add_ln_kernel<<<BE, 256>>>(states, t2, n2g, n2b, emask, states);
    }

    // 4. tokenizer projections
    tf32_big(states, t_kw, t_kb, kb, BE, Dd, Dd, 0);
    tf32_big(states, t_vw, t_vb, vb, BE, Dd, Dd, 0);
    sgemm_kernel<<<gemm_grid(Mm, Dd), 128>>>(mem_q, t_qw, t_qb, qb, Mm, Dd, Dd, 0);

    // 5. cross attention
    attn_kernel<<<dim3(Mm, Bb), 256>>>(emask, qb, kb, vb, mem);

    // 6. out proj + no-edge zeroing + llm projection
    keep_kernel<<<Bb, 256>>>(emask, keep);
    tf32_small(mem, t_ow, t_ob, memo, Bb * Mm, Dd, Dd, 0);
    scale_rows_kernel<<<Bb * Mm, 256>>>(memo, keep);
    tf32_small(memo, proj_w, proj_b, out, Bb * Mm, HLLM, Dd, 0);
}

// round 10
// speedup vs baseline: 2.5166x; 1.9972x over previous
#include <cuda_runtime.h>
#include <cuda_bf16.h>
#include <math.h>
#include <stdint.h>

// Problem constants
#define Bb 8
#define Ee 256
#define BE 2048        // B*E
#define Nn 32
#define Dd 512
#define RDd 768
#define Rr 2000
#define Ll 2
#define Kk 8
#define Mm 32
#define HEADS 8
#define DH 64
#define HLLM 4096

// ---------------- scratch (device globals; no allocation allowed) -------------
__device__ float g_proj[Rr * Dd];
__device__ float g_inv[Rr];
__device__ float g_states[BE * Dd];
__device__ float g_agg[BE * Dd];
__device__ float g_t2[BE * Dd];
__device__ float g_ffh[BE * 2048];
__device__ float g_kv[BE * 1024];        // fused K|V projections
__device__ float g_kvw[1024 * Dd];       // concat(t_kw, t_vw)
__device__ float g_kvb[1024];
__device__ float g_q[Mm * Dd];
__device__ float g_mem[Bb * Mm * Dd];
__device__ float g_memo[Bb * Mm * Dd];
__device__ float g_keep[Bb];
__device__ float g_vwT[Dd * Dd];         // vw transposed (per layer, reused)
__device__ float g_wc[Dd * Dd];          // folded ow@vw
__device__ float g_bc[Dd];               // folded ow@vb + ob
__device__ float g_zero[Dd];             // zero-initialized bias

// ---------------- tf32 helpers ------------------------------------------------
__device__ __forceinline__ uint32_t f2tf32(float x) {
    uint32_t u;
    asm("cvt.rna.tf32.f32 %0, %1;" : "=r"(u) : "f"(x));
    return u;
}

__device__ __forceinline__ void mma_tf32(float* d, const uint32_t* a, const uint32_t* b) {
    asm volatile(
        "mma.sync.aligned.m16n8k8.row.col.f32.tf32.tf32.f32 "
        "{%0,%1,%2,%3}, {%4,%5,%6,%7}, {%8,%9}, {%0,%1,%2,%3};"
        : "+f"(d[0]), "+f"(d[1]), "+f"(d[2]), "+f"(d[3])
        : "r"(a[0]), "r"(a[1]), "r"(a[2]), "r"(a[3]), "r"(b[0]), "r"(b[1]));
}

// ---------------- tf32 GEMM v2: C[M,N] = A[M,K] @ B[N,K]^T + bias -------------
// 256 threads / 8 warps, BK=32, 2-stage smem double buffer, dynamic smem.
// Requires M%BM==0, N%BN==0, K%64==0 (NS>=2).
template<int BM, int BN, int WM, int WN>
__global__ void __launch_bounds__(256) tf32_gemm_v2(
    const float* __restrict__ A, const float* __restrict__ B,
    const float* __restrict__ bias, float* __restrict__ C,
    int M, int N, int K, int act)
{
    constexpr int BK = 32;
    constexpr int LW = BK + 4;              // 36 words/row
    constexpr int WCOLS = BN / WN;
    constexpr int MF = WM / 16, NF = WN / 8;
    constexpr int AV = BM * 8 / 256;        // float4 loads per thread per stage
    constexpr int BV = BN * 8 / 256;

    extern __shared__ uint32_t dsm[];
    uint32_t* As = dsm;                      // [2][BM][LW]
    uint32_t* Bs = dsm + 2 * BM * LW;        // [2][BN][LW]

    const int bm = blockIdx.y * BM, bn = blockIdx.x * BN;
    const int tid = threadIdx.x, warp = tid >> 5, lane = tid & 31;
    const int wm = (warp / WCOLS) * WM, wn = (warp % WCOLS) * WN;
    const int g = lane >> 2, tg = lane & 3;

    // per-thread global-load coords (row, col4) fixed across k-steps
    int ar[AV], ac[AV], br[BV], bc_[BV];
#pragma unroll
    for (int v = 0; v < AV; v++) { int i = tid + v * 256; ar[v] = i >> 3; ac[v] = (i & 7) << 2; }
#pragma unroll
    for (int v = 0; v < BV; v++) { int i = tid + v * 256; br[v] = i >> 3; bc_[v] = (i & 7) << 2; }

    float acc[MF][NF][4];
#pragma unroll
    for (int f = 0; f < MF; f++)
#pragma unroll
        for (int j = 0; j < NF; j++)
#pragma unroll
            for (int c = 0; c < 4; c++) acc[f][j][c] = 0.f;

    float4 ra[AV], rb[BV];

    auto ldg = [&](int k0) {
#pragma unroll
        for (int v = 0; v < AV; v++)
            ra[v] = *(const float4*)(A + (size_t)(bm + ar[v]) * K + k0 + ac[v]);
#pragma unroll
        for (int v = 0; v < BV; v++)
            rb[v] = *(const float4*)(B + (size_t)(bn + br[v]) * K + k0 + bc_[v]);
    };
    auto sts = [&](int st) {
#pragma unroll
        for (int v = 0; v < AV; v++) {
            uint4 p;
            p.x = f2tf32(ra[v].x); p.y = f2tf32(ra[v].y);
            p.z = f2tf32(ra[v].z); p.w = f2tf32(ra[v].w);
            *(uint4*)&As[(st * BM + ar[v]) * LW + ac[v]] = p;
        }
#pragma unroll
        for (int v = 0; v < BV; v++) {
            uint4 p;
            p.x = f2tf32(rb[v].x); p.y = f2tf32(rb[v].y);
            p.z = f2tf32(rb[v].z); p.w = f2tf32(rb[v].w);
            *(uint4*)&Bs[(st * BN + br[v]) * LW + bc_[v]] = p;
        }
    };

    const int NS = K / BK;
    ldg(0);
    sts(0);
    if (NS > 1) ldg(BK);
    __syncthreads();

    for (int s = 0; s < NS; s++) {
        const int cur = s & 1;
        if (s + 1 < NS) sts(cur ^ 1);            // stage cur^1 free: synced after iter s-1
        if (s + 2 < NS) ldg((s + 2) * BK);       // overlap gmem with mma below
        const uint32_t* Ab = As + (size_t)cur * BM * LW;
        const uint32_t* Bbs = Bs + (size_t)cur * BN * LW;
#pragma unroll
        for (int kk = 0; kk < 4; kk++) {
            uint32_t afr[MF][4], bfr[NF][2];
#pragma unroll
            for (int f = 0; f < MF; f++) {
                int rm = wm + f * 16;
                afr[f][0] = Ab[(rm + g) * LW + kk * 8 + tg];
                afr[f][1] = Ab[(rm + g + 8) * LW + kk * 8 + tg];
                afr[f][2] = Ab[(rm + g) * LW + kk * 8 + tg + 4];
                afr[f][3] = Ab[(rm + g + 8) * LW + kk * 8 + tg + 4];
            }
#pragma unroll
            for (int j = 0; j < NF; j++) {
                int nb = wn + j * 8 + g;
                bfr[j][0] = Bbs[nb * LW + kk * 8 + tg];
                bfr[j][1] = Bbs[nb * LW + kk * 8 + tg + 4];
            }
#pragma unroll
            for (int f = 0; f < MF; f++)
#pragma unroll
                for (int j = 0; j < NF; j++)
                    mma_tf32(acc[f][j], afr[f], bfr[j]);
        }
        __syncthreads();
    }

#pragma unroll
    for (int f = 0; f < MF; f++) {
        int row0 = bm + wm + f * 16 + g;
#pragma unroll
        for (int j = 0; j < NF; j++) {
            int col = bn + wn + j * 8 + tg * 2;
            float bv0 = bias[col], bv1 = bias[col + 1];
            float c0 = acc[f][j][0] + bv0;
            float c1 = acc[f][j][1] + bv1;
            float c2 = acc[f][j][2] + bv0;
            float c3 = acc[f][j][3] + bv1;
            if (act == 1) {
                c0 = 0.5f * c0 * (1.f + erff(c0 * 0.70710678118654752440f));
                c1 = 0.5f * c1 * (1.f + erff(c1 * 0.70710678118654752440f));
                c2 = 0.5f * c2 * (1.f + erff(c2 * 0.70710678118654752440f));
                c3 = 0.5f * c3 * (1.f + erff(c3 * 0.70710678118654752440f));
            }
            *(float2*)(C + (size_t)row0 * N + col) = make_float2(c0, c1);
            *(float2*)(C + (size_t)(row0 + 8) * N + col) = make_float2(c2, c3);
        }
    }
}

// ---------------- fp32 SGEMM (exact path: proj table + tiny q proj) -----------
__global__ void __launch_bounds__(128) sgemm_kernel(
    const float* __restrict__ A, const float* __restrict__ B,
    const float* __restrict__ bias, float* __restrict__ C,
    int M, int N, int K, int act)
{
    __shared__ float As[8][128];
    __shared__ float Bs[8][64];
    const int bm = blockIdx.y * 128;
    const int bn = blockIdx.x * 64;
    const int tid = threadIdx.x;
    const int ty = tid >> 3;
    const int tx = tid & 7;

    float acc[8][8];
#pragma unroll
    for (int i = 0; i < 8; i++)
#pragma unroll
        for (int j = 0; j < 8; j++) acc[i][j] = 0.f;

    for (int k0 = 0; k0 < K; k0 += 8) {
#pragma unroll
        for (int v = 0; v < 2; v++) {
            int vid = tid + v * 128;
            int row = vid >> 1;
            int kp = (vid & 1) * 4;
            float4 a4 = make_float4(0.f, 0.f, 0.f, 0.f);
            int gm = bm + row;
            if (gm < M) a4 = *(const float4*)(A + (size_t)gm * K + k0 + kp);
            As[kp + 0][row] = a4.x;
            As[kp + 1][row] = a4.y;
            As[kp + 2][row] = a4.z;
            As[kp + 3][row] = a4.w;
        }
        {
            int row = tid >> 1;
            int kp = (tid & 1) * 4;
            float4 b4 = make_float4(0.f, 0.f, 0.f, 0.f);
            int gn = bn + row;
            if (gn < N) b4 = *(const float4*)(B + (size_t)gn * K + k0 + kp);
            Bs[kp + 0][row] = b4.x;
            Bs[kp + 1][row] = b4.y;
            Bs[kp + 2][row] = b4.z;
            Bs[kp + 3][row] = b4.w;
        }
        __syncthreads();
#pragma unroll
        for (int kk = 0; kk < 8; kk++) {
            float4 a0 = *(const float4*)&As[kk][ty * 8];
            float4 a1 = *(const float4*)&As[kk][ty * 8 + 4];
            float4 b0 = *(const float4*)&Bs[kk][tx * 8];
            float4 b1 = *(const float4*)&Bs[kk][tx * 8 + 4];
            float a[8] = {a0.x, a0.y, a0.z, a0.w, a1.x, a1.y, a1.z, a1.w};
            float b[8] = {b0.x, b0.y, b0.z, b0.w, b1.x, b1.y, b1.z, b1.w};
#pragma unroll
            for (int i = 0; i < 8; i++)
#pragma unroll
                for (int j = 0; j < 8; j++) acc[i][j] = fmaf(a[i], b[j], acc[i][j]);
        }
        __syncthreads();
    }

#pragma unroll
    for (int i = 0; i < 8; i++) {
        int gm = bm + ty * 8 + i;
        if (gm >= M) continue;
#pragma unroll
        for (int j = 0; j < 8; j++) {
            int gn = bn + tx * 8 + j;
            if (gn >= N) continue;
            float v = acc[i][j] + bias[gn];
            if (act == 1) v = 0.5f * v * (1.f + erff(v * 0.70710678118654752440f));
            C[(size_t)gm * N + gn] = v;
        }
    }
}

// ---------------- weight folding helpers --------------------------------------
// 512x512 transpose
__global__ void __launch_bounds__(256) transpose512_kernel(const float* __restrict__ in,
                                                           float* __restrict__ out)
{
    __shared__ float t[32][33];
    int bx = blockIdx.x * 32, by = blockIdx.y * 32;
    int x = threadIdx.x & 31, y4 = (threadIdx.x >> 5) * 4;
#pragma unroll
    for (int r = 0; r < 4; r++) t[y4 + r][x] = in[(size_t)(by + y4 + r) * Dd + bx + x];
    __syncthreads();
#pragma unroll
    for (int r = 0; r < 4; r++) out[(size_t)(bx + y4 + r) * Dd + by + x] = t[x][y4 + r];
}

// bc[n] = dot(ow[n,:], vb) + ob[n]
__global__ void __launch_bounds__(256) combine_bias_kernel(
    const float* __restrict__ ow, const float* __restrict__ vb,
    const float* __restrict__ ob, float* __restrict__ bc)
{
    int n = blockIdx.x * 256 + threadIdx.x;
    float s = 0.f;
    const float4* r = (const float4*)(ow + (size_t)n * Dd);
    const float4* v = (const float4*)vb;
#pragma unroll 4
    for (int k = 0; k < Dd / 4; k++) {
        float4 a = r[k], b = v[k];
        s += a.x * b.x + a.y * b.y + a.z * b.z + a.w * b.w;
    }
    bc[n] = s + ob[n];
}

// concat K/V weights + biases
__global__ void __launch_bounds__(256) copy_kv_kernel(
    const float* __restrict__ kw, const float* __restrict__ vw,
    const float* __restrict__ kb, const float* __restrict__ vb,
    float* __restrict__ kvw, float* __restrict__ kvb)
{
    int i = blockIdx.x * 256 + threadIdx.x;      // float4 index; total 2*512*512/4
    const int n4 = Dd * Dd / 4;
    float4* o = (float4*)kvw;
    if (i < n4) o[i] = ((const float4*)kw)[i];
    else o[i] = ((const float4*)vw)[i - n4];
    if (i < Dd) kvb[i] = kb[i];
    else if (i < 2 * Dd) kvb[i] = vb[i - Dd];
}

// ---------------- per-relation inverse norm -----------------------------------
__global__ void __launch_bounds__(128) invnorm_kernel(const float* __restrict__ proj,
                                                      float* __restrict__ inv)
{
    int r = blockIdx.x;
    int t = threadIdx.x;
    __shared__ float red[128];
    float s = 0.f;
    for (int i = t; i < Dd; i += 128) {
        float v = proj[(size_t)r * Dd + i];
        s += v * v;
    }
    red[t] = s;
    __syncthreads();
    for (int o = 64; o > 0; o >>= 1) {
        if (t < o) red[t] += red[t + o];
        __syncthreads();
    }
    if (t == 0) inv[r] = 1.f / fmaxf(sqrtf(red[0]), 1e-12f);
}

// ---------------- sims + top-k + aggregation (+ states init) ------------------
__global__ void __launch_bounds__(256) sim_topk_agg_kernel(
    const int* __restrict__ eids, const int* __restrict__ nids,
    const float* __restrict__ proj, const float* __restrict__ inv,
    float* __restrict__ states, float* __restrict__ agg)
{
    int be = blockIdx.x;
    int t = threadIdx.x;
    __shared__ float evec[Dd];
    __shared__ float sims[Nn];
    __shared__ int nid_s[Nn];
    __shared__ int sel[Kk];

    int eid = eids[be];
    for (int i = t; i < Dd; i += 256) {
        float v = proj[(size_t)eid * Dd + i];
        evec[i] = v;
        states[(size_t)be * Dd + i] = v;
    }
    if (t < Nn) nid_s[t] = nids[be * Nn + t];
    __syncthreads();

    int warp = t >> 5, lane = t & 31;
    float einv = inv[eid];
    for (int n = warp; n < Nn; n += 8) {
        int nid = nid_s[n];
        const float* nv = proj + (size_t)nid * Dd;
        float s = 0.f;
        for (int i = lane; i < Dd; i += 32) s += nv[i] * evec[i];
#pragma unroll
        for (int o = 16; o > 0; o >>= 1) s += __shfl_down_sync(0xffffffffu, s, o);
        if (lane == 0) sims[n] = s * einv * inv[nid];
    }
    __syncthreads();

    if (t == 0) {
        unsigned used = 0;
        for (int k = 0; k < Kk; k++) {
            float best = -1e30f;
            int bi = 0;
            for (int n = 0; n < Nn; n++) {
                if (used & (1u << n)) continue;
                if (sims[n] > best) { best = sims[n]; bi = n; }
            }
            used |= (1u << bi);
            sel[k] = nid_s[bi];
        }
    }
    __syncthreads();

    for (int i = t; i < Dd; i += 256) {
        float s = 0.f;
#pragma unroll
        for (int k = 0; k < Kk; k++) s += proj[(size_t)sel[k] * Dd + i];
        agg[(size_t)be * Dd + i] = s * 0.125f;
    }
}

// ---------------- residual add + layernorm (+ optional mask) ------------------
__global__ void __launch_bounds__(256) add_ln_kernel(
    const float* __restrict__ x, const float* __restrict__ r,
    const float* __restrict__ g, const float* __restrict__ b,
    const float* __restrict__ mask, float* __restrict__ out)
{
    int row = blockIdx.x;
    int t = threadIdx.x;
    __shared__ float red[256];
    size_t base = (size_t)row * Dd;
    float v0 = x[base + t] + r[base + t];
    float v1 = x[base + t + 256] + r[base + t + 256];

    red[t] = v0 + v1;
    __syncthreads();
    for (int o = 128; o > 0; o >>= 1) {
        if (t < o) red[t] += red[t + o];
        __syncthreads();
    }
    float mu = red[0] * (1.f / 512.f);
    __syncthreads();

    float d0 = v0 - mu, d1 = v1 - mu;
    red[t] = d0 * d0 + d1 * d1;
    __syncthreads();
    for (int o = 128; o > 0; o >>= 1) {
        if (t < o) red[t] += red[t + o];
        __syncthreads();
    }
    float var = red[0] * (1.f / 512.f);
    float is = rsqrtf(var + 1e-5f);
    float mk = mask ? mask[row] : 1.f;
    out[base + t]       = (d0 * is * g[t] + b[t]) * mk;
    out[base + t + 256] = (d1 * is * g[t + 256] + b[t + 256]) * mk;
}

// ---------------- memory-token cross attention (fused KV layout) --------------
__global__ void __launch_bounds__(256) attn_kernel(
    const float* __restrict__ emask, const float* __restrict__ q,
    const float* __restrict__ kv, float* __restrict__ mem)
{
    int m = blockIdx.x, b = blockIdx.y;
    int h = threadIdx.x >> 5, lane = threadIdx.x & 31;
    __shared__ float w[HEADS][Ee];
    __shared__ float qs[HEADS][DH];

    for (int i = lane; i < DH; i += 32) qs[h][i] = q[(size_t)m * Dd + h * DH + i];
    __syncwarp();

    float sc[8];
#pragma unroll
    for (int i = 0; i < 8; i++) {
        int e = lane + i * 32;
        const float* kk = kv + ((size_t)(b * Ee + e)) * 1024 + h * DH;
        float s = 0.f;
#pragma unroll
        for (int d = 0; d < DH; d += 4) {
            float4 kvv = *(const float4*)(kk + d);
            float4 qv = *(const float4*)(&qs[h][d]);
            s += qv.x * kvv.x + qv.y * kvv.y + qv.z * kvv.z + qv.w * kvv.w;
        }
        s *= 0.125f;
        if (emask[b * Ee + e] == 0.f) s = -3.402823466e38f;
        sc[i] = s;
    }
    float mx = sc[0];
#pragma unroll
    for (int i = 1; i < 8; i++) mx = fmaxf(mx, sc[i]);
#pragma unroll
    for (int o = 16; o > 0; o >>= 1) mx = fmaxf(mx, __shfl_xor_sync(0xffffffffu, mx, o));
    float sum = 0.f;
#pragma unroll
    for (int i = 0; i < 8; i++) {
        sc[i] = expf(sc[i] - mx);
        sum += sc[i];
    }
#pragma unroll
    for (int o = 16; o > 0; o >>= 1) sum += __shfl_xor_sync(0xffffffffu, sum, o);
    float invs = 1.f / sum;
#pragma unroll
    for (int i = 0; i < 8; i++) w[h][lane + i * 32] = sc[i] * invs;
    __syncwarp();

    int d0 = lane * 2;
    float o0 = 0.f, o1 = 0.f;
    for (int e = 0; e < Ee; e++) {
        float we = w[h][e];
        const float2 vv = *(const float2*)(kv + ((size_t)(b * Ee + e)) * 1024 + 512 + h * DH + d0);
        o0 = fmaf(we, vv.x, o0);
        o1 = fmaf(we, vv.y, o1);
    }
    size_t ob = ((size_t)(b * Mm + m)) * Dd + h * DH + d0;
    mem[ob] = o0;
    mem[ob + 1] = o1;
}

// ---------------- no-edge flag + row scaling ----------------------------------
__global__ void __launch_bounds__(256) keep_kernel(const float* __restrict__ emask,
                                                   float* __restrict__ keep)
{
    int b = blockIdx.x, t = threadIdx.x;
    __shared__ float red[256];
    red[t] = emask[b * Ee + t];
    __syncthreads();
    for (int o = 128; o > 0; o >>= 1) {
        if (t < o) red[t] += red[t + o];
        __syncthreads();
    }
    if (t == 0) keep[b] = (red[0] == 0.f) ? 0.f : 1.f;
}

__global__ void __launch_bounds__(256) scale_rows_kernel(float* __restrict__ memo,
                                                         const float* __restrict__ keep)
{
    int row = blockIdx.x, t = threadIdx.x;
    float kf = keep[row >> 5];
    memo[(size_t)row * Dd + t] *= kf;
    memo[(size_t)row * Dd + t + 256] *= kf;
}

// ---------------- launchers ---------------------------------------------------
static inline dim3 gemm_grid(int M, int N) { return dim3((N + 63) / 64, (M + 127) / 128); }

template<int BM, int BN>
static constexpr int smem_bytes() { return 2 * (BM + BN) * 36 * 4; }

static inline void gemmA(const float* A, const float* B, const float* bias, float* C,
                         int M, int N, int K, int act) {  // 128x128 (FFN1)
    cudaFuncSetAttribute(tf32_gemm_v2<128, 128, 64, 32>,
                         cudaFuncAttributeMaxDynamicSharedMemorySize, smem_bytes<128, 128>());
    tf32_gemm_v2<128, 128, 64, 32><<<dim3(N / 128, M / 128), 256, smem_bytes<128, 128>()>>>(
        A, B, bias, C, M, N, K, act);
}
static inline void gemmB(const float* A, const float* B, const float* bias, float* C,
                         int M, int N, int K, int act) {  // 128x64
    cudaFuncSetAttribute(tf32_gemm_v2<128, 64, 32, 32>,
                         cudaFuncAttributeMaxDynamicSharedMemorySize, smem_bytes<128, 64>());
    tf32_gemm_v2<128, 64, 32, 32><<<dim3(N / 64, M / 128), 256, smem_bytes<128, 64>()>>>(
        A, B, bias, C, M, N, K, act);
}
static inline void gemmC(const float* A, const float* B, const float* bias, float* C,
                         int M, int N, int K, int act) {  // 64x64 (small M)
    cudaFuncSetAttribute(tf32_gemm_v2<64, 64, 16, 32>,
                         cudaFuncAttributeMaxDynamicSharedMemorySize, smem_bytes<64, 64>());
    tf32_gemm_v2<64, 64, 16, 32><<<dim3(N / 64, M / 64), 256, smem_bytes<64, 64>()>>>(
        A, B, bias, C, M, N, K, act);
}

extern "C" void kernel_launch(void* const* d_in, const int* in_sizes, int n_in,
                              void* d_out, int out_size)
{
    const int*   eids    = (const int*)d_in[0];
    const int*   nids    = (const int*)d_in[1];
    const float* emask   = (const float*)d_in[2];
    const float* rel_emb = (const float*)d_in[3];
    const float* rp_w    = (const float*)d_in[4];
    const float* rp_b    = (const float*)d_in[5];
    const float* ly_vw   = (const float*)d_in[6];
    const float* ly_vb   = (const float*)d_in[7];
    const float* ly_ow   = (const float*)d_in[8];
    const float* ly_ob   = (const float*)d_in[9];
    const float* ly_n1g  = (const float*)d_in[10];
    const float* ly_n1b  = (const float*)d_in[11];
    const float* ly_n2g  = (const float*)d_in[12];
    const float* ly_n2b  = (const float*)d_in[13];
    const float* ly_w1   = (const float*)d_in[14];
    const float* ly_b1   = (const float*)d_in[15];
    const float* ly_w2   = (const float*)d_in[16];
    const float* ly_b2   = (const float*)d_in[17];
    const float* mem_q   = (const float*)d_in[18];
    const float* t_qw    = (const float*)d_in[19];
    const float* t_qb    = (const float*)d_in[20];
    const float* t_kw    = (const float*)d_in[21];
    const float* t_kb    = (const float*)d_in[22];
    const float* t_vw    = (const float*)d_in[23];
    const float* t_vb    = (const float*)d_in[24];
    const float* t_ow    = (const float*)d_in[25];
    const float* t_ob    = (const float*)d_in[26];
    const float* proj_w  = (const float*)d_in[27];
    const float* proj_b  = (const float*)d_in[28];
    float* out = (float*)d_out;

    float *proj, *inv, *states, *agg, *t2, *ffh, *kv, *kvw, *kvb, *qb, *mem, *memo, *keep;
    float *vwT, *wc, *bcb, *zero;
    cudaGetSymbolAddress((void**)&proj,   g_proj);
    cudaGetSymbolAddress((void**)&inv,    g_inv);
    cudaGetSymbolAddress((void**)&states, g_states);
    cudaGetSymbolAddress((void**)&agg,    g_agg);
    cudaGetSymbolAddress((void**)&t2,     g_t2);
    cudaGetSymbolAddress((void**)&ffh,    g_ffh);
    cudaGetSymbolAddress((void**)&kv,     g_kv);
    cudaGetSymbolAddress((void**)&kvw,    g_kvw);
    cudaGetSymbolAddress((void**)&kvb,    g_kvb);
    cudaGetSymbolAddress((void**)&qb,     g_q);
    cudaGetSymbolAddress((void**)&mem,    g_mem);
    cudaGetSymbolAddress((void**)&memo,   g_memo);
    cudaGetSymbolAddress((void**)&keep,   g_keep);
    cudaGetSymbolAddress((void**)&vwT,    g_vwT);
    cudaGetSymbolAddress((void**)&wc,     g_wc);
    cudaGetSymbolAddress((void**)&bcb,    g_bc);
    cudaGetSymbolAddress((void**)&zero,   g_zero);

    // 1. exact fp32 relation-table projection (protects discrete top-k)
    sgemm_kernel<<<gemm_grid(Rr, Dd), 128>>>(rel_emb, rp_w, rp_b, proj, Rr, Dd, RDd, 0);
    invnorm_kernel<<<Rr, 128>>>(proj, inv);

    // 2. sims + top-k + aggregation (+ states := rel_vec)
    sim_topk_agg_kernel<<<BE, 256>>>(eids, nids, proj, inv, states, agg);

    // prepare fused KV weights (independent of the above; just queued on stream)
    copy_kv_kernel<<<512, 256>>>(t_kw, t_vw, t_kb, t_vb, kvw, kvb);

    // 3. relation context layers
    for (int l = 0; l < Ll; l++) {
        const float* vw  = ly_vw + (size_t)l * Dd * Dd;
        const float* vbi = ly_vb + (size_t)l * Dd;
        const float* ow  = ly_ow + (size_t)l * Dd * Dd;
        const float* ob  = ly_ob + (size_t)l * Dd;
        const float* n1g = ly_n1g + (size_t)l * Dd;
        const float* n1b = ly_n1b + (size_t)l * Dd;
        const float* n2g = ly_n2g + (size_t)l * Dd;
        const float* n2b = ly_n2b + (size_t)l * Dd;
        const float* w1  = ly_w1 + (size_t)l * 4 * Dd * Dd;
        const float* b1  = ly_b1 + (size_t)l * 4 * Dd;
        const float* w2  = ly_w2 + (size_t)l * Dd * 4 * Dd;
        const float* b2  = ly_b2 + (size_t)l * Dd;

        // fold v/o: wc = ow @ vw (via vw^T), bc = ow@vb + ob
        transpose512_kernel<<<dim3(16, 16), 256>>>(vw, vwT);
        gemmC(ow, vwT, zero, wc, Dd, Dd, Dd, 0);
        combine_bias_kernel<<<2, 256>>>(ow, vbi, ob, bcb);

        gemmB(agg, wc, bcb, t2, BE, Dd, Dd, 0);                 // attn (folded)
        add_ln_kernel<<<BE, 256>>>(states, t2, n1g, n1b, nullptr, states);
        gemmA(states, w1, b1, ffh, BE, 4 * Dd, Dd, 1);          // FFN1 + gelu
        gemmB(ffh, w2, b2, t2, BE, Dd, 4 * Dd, 0);              // FFN2
        add_ln_kernel<<<BE, 256>>>(states, t2, n2g, n2b, emask, states);
    }

    // 4. fused K|V projection + q projection
    gemmB(states, kvw, kvb, kv, BE, 1024, Dd, 0);
    sgemm_kernel<<<gemm_grid(Mm, Dd), 128>>>(mem_q, t_qw, t_qb, qb, Mm, Dd, Dd, 0);

    // 5. cross attention
    attn_kernel<<<dim3(Mm, Bb), 256>>>(emask, qb, kv, mem);

    // 6. out proj + no-edge zeroing + llm projection
    keep_kernel<<<Bb, 256>>>(emask, keep);
    gemmC(mem, t_ow, t_ob, memo, Bb * Mm, Dd, Dd, 0);
    scale_rows_kernel<<<Bb * Mm, 256>>>(memo, keep);
    gemmC(memo, proj_w, proj_b, out, Bb * Mm, HLLM, Dd, 0);
}